// round 9
// baseline (speedup 1.0000x reference)
#include <cuda_runtime.h>
#include <cuda_fp16.h>
#include <math.h>
#include <stdint.h>

#define B_    256
#define D_    2048
#define NM    16384      // C_CAM * P
#define P_    2048
#define CCAM  8
#define KTOP  50
#define TINV  (1.0f/0.07f)

// scratch (static device globals — no allocation allowed)
__device__ __align__(16) uint32_t g_xh[B_ * D_ / 2];   // fp16 normalized inputs, 1 MB
__device__ float g_logits[B_ * NM];                    // all_logits, 16 MB
__device__ float g_ce[B_];
__device__ float g_lossk[B_];
__device__ int   g_cnt = 0;                            // last-CTA counter

// ---------------------------------------------------------------------------
__device__ __forceinline__ uint32_t smem_u32(const void* p) {
    uint32_t a;
    asm("{ .reg .u64 t; cvta.to.shared.u64 t, %1; cvt.u32.u64 %0, t; }"
        : "=r"(a) : "l"(p));
    return a;
}
__device__ __forceinline__ void cpa16(uint32_t s, const void* g) {
    asm volatile("cp.async.cg.shared.global [%0], [%1], 16;" :: "r"(s), "l"(g) : "memory");
}
__device__ __forceinline__ uint32_t packh(float lo, float hi) {
    uint32_t r;
    asm("cvt.rn.f16x2.f32 %0, %1, %2;" : "=r"(r) : "f"(hi), "f"(lo));
    return r;
}
__device__ __forceinline__ uint32_t ordu(float f) {
    uint32_t u = __float_as_uint(f);
    return (u & 0x80000000u) ? ~u : (u | 0x80000000u);
}
#define LDSM4(r0, r1, r2, r3, a) \
    asm volatile("ldmatrix.sync.aligned.m8n8.x4.shared.b16 {%0,%1,%2,%3}, [%4];" \
                 : "=r"(r0), "=r"(r1), "=r"(r2), "=r"(r3) : "r"(a))

// ---------------------------------------------------------------------------
// Kernel 1: L2-normalize each input row -> fp16 (single pass, register row)
// ---------------------------------------------------------------------------
__global__ void __launch_bounds__(256) knorm(const float* __restrict__ x) {
    __shared__ float red[8];
    int b = blockIdx.x, t = threadIdx.x;
    const float4* row = (const float4*)(x + (size_t)b * D_);
    float4 v0 = row[2 * t], v1 = row[2 * t + 1];
    float s = v0.x * v0.x + v0.y * v0.y + v0.z * v0.z + v0.w * v0.w
            + v1.x * v1.x + v1.y * v1.y + v1.z * v1.z + v1.w * v1.w;
    #pragma unroll
    for (int o = 16; o > 0; o >>= 1) s += __shfl_down_sync(0xffffffffu, s, o);
    if ((t & 31) == 0) red[t >> 5] = s;
    __syncthreads();
    if (t < 8) {
        float w = red[t];
        #pragma unroll
        for (int o = 4; o > 0; o >>= 1) w += __shfl_down_sync(0xffu, w, o);
        if (t == 0) red[0] = w;
    }
    __syncthreads();
    float inv = rsqrtf(red[0]);
    uint4 o;
    o.x = packh(v0.x * inv, v0.y * inv);
    o.y = packh(v0.z * inv, v0.w * inv);
    o.z = packh(v1.x * inv, v1.y * inv);
    o.w = packh(v1.z * inv, v1.w * inv);
    ((uint4*)g_xh)[b * (D_ / 8) + t] = o;
}

// ---------------------------------------------------------------------------
// Kernel 2: fp16 GEMM  C[256,16384] = xh @ tempV^T
// CTA 256x64 (tempV read once). 3-stage cp.async pipeline, 1 barrier/chunk.
// A: fp16 smem + ldmatrix.  B: fp32 staging smem -> LDS.64 + cvt -> mma regs.
// ---------------------------------------------------------------------------
#define BMT 256
#define BNT 64
#define BKH 32                    // halfs per K chunk
#define NCHG (D_ / BKH)           // 64
#define ROWA 80                   // A row: 64 B data + 16 pad (LDSM-safe)
#define ROWB32 160                // B fp32 row: 128 B data + 32 pad (LDS.64-safe)
#define ASTG (BMT * ROWA)         // 20480 B
#define B32S (BNT * ROWB32)       // 10240 B
#define STG  (ASTG + B32S)        // 30720 B
#define NSTAGE 3
#define GEMM_SMEM (NSTAGE * STG)  // 92160 B

__global__ void __launch_bounds__(256, 2) kgemm(const float* __restrict__ Bmat) {
    extern __shared__ char sm[];
    uint32_t sbase = smem_u32(sm);
    int t = threadIdx.x, lane = t & 31, wid = t >> 5;
    int warp_m = (wid & 3) * 64, warp_n = (wid >> 2) * 32;
    int gid = lane >> 2, tig = lane & 3;
    int nBase = blockIdx.x * BNT;

    float acc[4][4][4];
    #pragma unroll
    for (int i = 0; i < 4; i++)
        #pragma unroll
        for (int j = 0; j < 4; j++)
            #pragma unroll
            for (int q = 0; q < 4; q++) acc[i][j][q] = 0.f;

    const char* xhb = (const char*)g_xh;

    auto loadAB = [&](int stage, int c) {
        int k0 = c * BKH;
        uint32_t As = sbase + stage * STG;
        uint32_t B3 = As + ASTG;
        // A: 256 rows x 64 B -> 4 cp.async/thread
        #pragma unroll
        for (int r = 0; r < 4; r++) {
            int i = t + r * 256, row = i >> 2, q = i & 3;
            cpa16(As + (uint32_t)(row * ROWA + q * 16),
                  xhb + ((size_t)row * D_ + k0 + q * 8) * 2);
        }
        // B fp32: 64 rows x 128 B -> 2 cp.async/thread
        #pragma unroll
        for (int r = 0; r < 2; r++) {
            int i = t + r * 256, row = i >> 3, q = i & 7;
            cpa16(B3 + (uint32_t)(row * ROWB32 + q * 16),
                  Bmat + (size_t)(nBase + row) * D_ + k0 + q * 4);
        }
    };

    uint32_t aoff = (uint32_t)((lane & 15) * ROWA + (lane >> 4) * 16);
    // per-lane B base: n = warp_n + (lane>>2), k-pair offset (lane&3)*2 floats
    uint32_t bb = (uint32_t)((warp_n + (lane >> 2)) * ROWB32 + (lane & 3) * 8);

    loadAB(0, 0); asm volatile("cp.async.commit_group;" ::: "memory");
    loadAB(1, 1); asm volatile("cp.async.commit_group;" ::: "memory");

    for (int c = 0; c < NCHG; c++) {
        int s = c % NSTAGE;
        asm volatile("cp.async.wait_group 1;" ::: "memory");
        __syncthreads();
        // prefetch chunk c+2 into the stage computed last iteration (safe)
        if (c + 2 < NCHG) loadAB((c + 2) % NSTAGE, c + 2);
        asm volatile("cp.async.commit_group;" ::: "memory");

        uint32_t As = sbase + s * STG;
        uint32_t Bs = As + ASTG + bb;
        #pragma unroll
        for (int kk = 0; kk < 2; kk++) {
            uint32_t a[4][4], b[4][2];
            #pragma unroll
            for (int mt = 0; mt < 4; mt++) {
                uint32_t ad = As + (uint32_t)((warp_m + mt * 16) * ROWA + kk * 32) + aoff;
                LDSM4(a[mt][0], a[mt][1], a[mt][2], a[mt][3], ad);
            }
            #pragma unroll
            for (int nt = 0; nt < 4; nt++) {
                uint32_t bd = Bs + (uint32_t)(nt * 8 * ROWB32 + kk * 64);
                float2 u, v;
                asm volatile("ld.shared.v2.f32 {%0,%1}, [%2];"
                             : "=f"(u.x), "=f"(u.y) : "r"(bd));
                asm volatile("ld.shared.v2.f32 {%0,%1}, [%2];"
                             : "=f"(v.x), "=f"(v.y) : "r"(bd + 32));
                b[nt][0] = packh(u.x, u.y);
                b[nt][1] = packh(v.x, v.y);
            }
            #pragma unroll
            for (int mt = 0; mt < 4; mt++)
                #pragma unroll
                for (int nt = 0; nt < 4; nt++)
                    asm volatile(
                        "mma.sync.aligned.m16n8k16.row.col.f32.f16.f16.f32 "
                        "{%0,%1,%2,%3},{%4,%5,%6,%7},{%8,%9},{%0,%1,%2,%3};"
                        : "+f"(acc[mt][nt][0]), "+f"(acc[mt][nt][1]),
                          "+f"(acc[mt][nt][2]), "+f"(acc[mt][nt][3])
                        : "r"(a[mt][0]), "r"(a[mt][1]), "r"(a[mt][2]), "r"(a[mt][3]),
                          "r"(b[nt][0]), "r"(b[nt][1]));
        }
    }

    #pragma unroll
    for (int mt = 0; mt < 4; mt++) {
        int row0 = warp_m + mt * 16 + gid;
        #pragma unroll
        for (int nt = 0; nt < 4; nt++) {
            int col = nBase + warp_n + nt * 8 + 2 * tig;
            *(float2*)(g_logits + (size_t)row0 * NM + col) =
                make_float2(acc[mt][nt][0], acc[mt][nt][1]);
            *(float2*)(g_logits + (size_t)(row0 + 8) * NM + col) =
                make_float2(acc[mt][nt][2], acc[mt][nt][3]);
        }
    }
}

// ---------------------------------------------------------------------------
// Kernel 3: per-sample reductions; 3-pass radix select + fused finalize
// ---------------------------------------------------------------------------
__device__ __forceinline__ float blockSumF(float v, float* scratch) {
    int t = threadIdx.x;
    #pragma unroll
    for (int o = 16; o > 0; o >>= 1) v += __shfl_down_sync(0xffffffffu, v, o);
    if ((t & 31) == 0) scratch[t >> 5] = v;
    __syncthreads();
    if (t < 8) {
        float w = scratch[t];
        #pragma unroll
        for (int o = 4; o > 0; o >>= 1) w += __shfl_down_sync(0xffu, w, o);
        if (t == 0) scratch[0] = w;
    }
    __syncthreads();
    float r = scratch[0];
    __syncthreads();
    return r;
}

__global__ void __launch_bounds__(256) krow(const int* __restrict__ labels,
                                            const int* __restrict__ cams,
                                            float* __restrict__ out) {
    extern __shared__ float sv[];                 // NM floats (64 KB)
    __shared__ int hist[2048];
    __shared__ float fred[8];
    __shared__ int wtot[8], wexcl[8];
    __shared__ float s_ori[CCAM];
    __shared__ uint32_t s_prefix;
    __shared__ int s_rem;
    __shared__ int s_last;
    __shared__ int sc_cam[B_];
    __shared__ float sce[B_], slk[B_];

    int b = blockIdx.x;
    int t = threadIdx.x;
    int lane = t & 31, wid = t >> 5;

    #pragma unroll
    for (int j = 0; j < 8; j++) hist[t + 256 * j] = 0;
    __syncthreads();

    // ---- load row + pass-0 histogram (bits 31:21) fused ----
    const float4* row4 = (const float4*)(g_logits + (size_t)b * NM);
    #pragma unroll
    for (int j = 0; j < 16; j++) {
        float4 w = row4[t + 256 * j];
        ((float4*)sv)[t + 256 * j] = w;
        atomicAdd(&hist[ordu(w.x) >> 21], 1);
        atomicAdd(&hist[ordu(w.y) >> 21], 1);
        atomicAdd(&hist[ordu(w.z) >> 21], 1);
        atomicAdd(&hist[ordu(w.w) >> 21], 1);
    }
    __syncthreads();

    int cam = cams[b];
    int lab = labels[b];

    // ---- intra-camera CE, fixed shift m=1 (|cosine| <= 1), unmasked ----
    int base = cam * P_;
    float s = 0.f;
    #pragma unroll 4
    for (int i = t; i < P_; i += 256) s += expf((sv[base + i] - 1.0f) * TINV);
    float sall = blockSumF(s, fred);
    if (t == 0) g_ce[b] = TINV + logf(sall) - sv[base + lab] * TINV;
    __syncthreads();

    // ---- capture positives, mask them, fix pass-0 histogram ----
    if (t == 0) {
        #pragma unroll
        for (int c = 0; c < CCAM; c++) {
            float v = sv[lab + P_ * c];
            s_ori[c] = v;
            hist[ordu(v) >> 21] -= 1;
            sv[lab + P_ * c] = -10000.0f;
        }
    }
    __syncthreads();

    // ---- hierarchical bin selection ----
    uint32_t prefix = 0u;
    int rem = KTOP;

    auto selectBins = [&](int nbpt, int shift) {
        int h[8], tot = 0;
        for (int j = 0; j < nbpt; j++) { h[j] = hist[t * nbpt + j]; tot += h[j]; }
        int suf = tot;
        #pragma unroll
        for (int o = 1; o < 32; o <<= 1) {
            int q = __shfl_down_sync(0xffffffffu, suf, o);
            if (lane + o < 32) suf += q;
        }
        if (lane == 0) wtot[wid] = suf;
        __syncthreads();
        if (t < 8) {
            int w = wtot[t], ws = w;
            #pragma unroll
            for (int o = 1; o < 8; o <<= 1) {
                int q = __shfl_down_sync(0xffu, ws, o);
                if (t + o < 8) ws += q;
            }
            wexcl[t] = ws - w;
        }
        __syncthreads();
        int above = wexcl[wid] + (suf - tot);
        for (int j = nbpt - 1; j >= 0; j--) {
            int incl = above + h[j];
            if (above < rem && rem <= incl) {
                s_prefix = prefix | ((uint32_t)(t * nbpt + j) << shift);
                s_rem = rem - above;
            }
            above = incl;
        }
        __syncthreads();
        prefix = s_prefix;
        rem = s_rem;
    };

    // pass 0: bits 31:21 (2048 bins) — histogram already built
    selectBins(8, 21);

    // pass 1: bits 20:10 (2048 bins)
    __syncthreads();
    #pragma unroll
    for (int j = 0; j < 8; j++) hist[t + 256 * j] = 0;
    __syncthreads();
    #pragma unroll 8
    for (int j = 0; j < NM / 256; j++) {
        uint32_t u = ordu(sv[t + 256 * j]);
        if ((u & 0xFFE00000u) == prefix)
            atomicAdd(&hist[(u >> 10) & 0x7FF], 1);
    }
    __syncthreads();
    selectBins(8, 10);

    // pass 2: bits 9:0 (1024 bins)
    __syncthreads();
    #pragma unroll
    for (int j = 0; j < 4; j++) hist[t + 256 * j] = 0;
    __syncthreads();
    #pragma unroll 8
    for (int j = 0; j < NM / 256; j++) {
        uint32_t u = ordu(sv[t + 256 * j]);
        if ((u & 0xFFFFFC00u) == prefix)
            atomicAdd(&hist[u & 0x3FF], 1);
    }
    __syncthreads();
    selectBins(4, 0);

    uint32_t thr = prefix;
    float tf = (thr & 0x80000000u) ? __uint_as_float(thr ^ 0x80000000u)
                                   : __uint_as_float(~thr);

    // ---- sum exp over values strictly above threshold (m = 1) ----
    float ssum = 0.f;
    #pragma unroll 8
    for (int j = 0; j < NM / 256; j++) {
        float v = sv[t + 256 * j];
        if (ordu(v) > thr) ssum += expf((v - 1.0f) * TINV);
    }
    float tot = blockSumF(ssum, fred);
    if (t == 0) {
        tot += (float)rem * expf((tf - 1.0f) * TINV);    // ties at threshold
        float mean = 0.f;
        #pragma unroll
        for (int c = 0; c < CCAM; c++) {
            tot += expf((s_ori[c] - 1.0f) * TINV);
            mean += s_ori[c];
        }
        g_lossk[b] = TINV + logf(tot) - mean * TINV / (float)CCAM;
    }

    // ---- fused finalize: last CTA computes segment means ----
    if (t == 0) {
        __threadfence();
        int prev = atomicAdd(&g_cnt, 1);
        s_last = (prev == B_ - 1) ? 1 : 0;
    }
    __syncthreads();
    if (!s_last) return;
    if (t == 0) g_cnt = 0;
    volatile float* vce = g_ce;
    volatile float* vlk = g_lossk;
    sc_cam[t] = cams[t];
    sce[t] = vce[t];
    slk[t] = vlk[t];
    __syncthreads();
    __shared__ float mce[CCAM], mlk[CCAM];
    if (t < CCAM) {
        float sc = 0.f, sl = 0.f; int cnt = 0;
        for (int i = 0; i < B_; i++) {
            if (sc_cam[i] == t) { sc += sce[i]; sl += slk[i]; cnt++; }
        }
        mce[t] = (cnt > 0) ? sc / (float)cnt : 0.f;
        mlk[t] = (cnt > 0) ? sl / (float)cnt : 0.f;
    }
    __syncthreads();
    if (t == 0) {
        float li = 0.f, lk = 0.f;
        #pragma unroll
        for (int c = 0; c < CCAM; c++) { li += mce[c]; lk += mlk[c]; }
        out[0] = li;
        out[1] = 0.5f * lk;                 // LOSS_WEIGHT
    }
}

// ---------------------------------------------------------------------------
extern "C" void kernel_launch(void* const* d_in, const int* in_sizes, int n_in,
                              void* d_out, int out_size) {
    const float* x      = (const float*)d_in[0];
    const int*   labels = (const int*)d_in[1];
    const int*   cams   = (const int*)d_in[2];
    const float* tempV  = (const float*)d_in[3];
    float* out = (float*)d_out;

    knorm<<<B_, 256>>>(x);

    cudaFuncSetAttribute(kgemm, cudaFuncAttributeMaxDynamicSharedMemorySize,
                         GEMM_SMEM);
    kgemm<<<NM / BNT, 256, GEMM_SMEM>>>(tempV);    // 256 CTAs

    cudaFuncSetAttribute(krow, cudaFuncAttributeMaxDynamicSharedMemorySize,
                         NM * (int)sizeof(float) + 1024);
    krow<<<B_, 256, NM * sizeof(float)>>>(labels, cams, out);
}

// round 10
// speedup vs baseline: 1.1064x; 1.1064x over previous
#include <cuda_runtime.h>
#include <cuda_fp16.h>
#include <math.h>
#include <stdint.h>

#define B_    256
#define D_    2048
#define NM    16384      // C_CAM * P
#define P_    2048
#define CCAM  8
#define KTOP  50
#define TINV  (1.0f/0.07f)

// scratch (static device globals — no allocation allowed)
__device__ __align__(16) uint32_t g_xh[B_ * D_ / 2];   // fp16 normalized inputs, 1 MB
__device__ float g_logits[B_ * NM];                    // all_logits, 16 MB
__device__ float g_ce[B_];
__device__ float g_lossk[B_];
__device__ int   g_cnt = 0;                            // last-CTA counter

// ---------------------------------------------------------------------------
__device__ __forceinline__ uint32_t smem_u32(const void* p) {
    uint32_t a;
    asm("{ .reg .u64 t; cvta.to.shared.u64 t, %1; cvt.u32.u64 %0, t; }"
        : "=r"(a) : "l"(p));
    return a;
}
__device__ __forceinline__ void cpa16(uint32_t s, const void* g) {
    asm volatile("cp.async.cg.shared.global [%0], [%1], 16;" :: "r"(s), "l"(g) : "memory");
}
__device__ __forceinline__ uint32_t packh(float lo, float hi) {
    uint32_t r;
    asm("cvt.rn.f16x2.f32 %0, %1, %2;" : "=r"(r) : "f"(hi), "f"(lo));
    return r;
}
__device__ __forceinline__ uint32_t ordu(float f) {
    uint32_t u = __float_as_uint(f);
    return (u & 0x80000000u) ? ~u : (u | 0x80000000u);
}
#define LDSM4(r0, r1, r2, r3, a) \
    asm volatile("ldmatrix.sync.aligned.m8n8.x4.shared.b16 {%0,%1,%2,%3}, [%4];" \
                 : "=r"(r0), "=r"(r1), "=r"(r2), "=r"(r3) : "r"(a))

// ---------------------------------------------------------------------------
// Kernel 1: L2-normalize each input row -> fp16 (single pass, register row)
// ---------------------------------------------------------------------------
__global__ void __launch_bounds__(256) knorm(const float* __restrict__ x) {
    __shared__ float red[8];
    int b = blockIdx.x, t = threadIdx.x;
    const float4* row = (const float4*)(x + (size_t)b * D_);
    float4 v0 = row[2 * t], v1 = row[2 * t + 1];
    float s = v0.x * v0.x + v0.y * v0.y + v0.z * v0.z + v0.w * v0.w
            + v1.x * v1.x + v1.y * v1.y + v1.z * v1.z + v1.w * v1.w;
    #pragma unroll
    for (int o = 16; o > 0; o >>= 1) s += __shfl_down_sync(0xffffffffu, s, o);
    if ((t & 31) == 0) red[t >> 5] = s;
    __syncthreads();
    if (t < 8) {
        float w = red[t];
        #pragma unroll
        for (int o = 4; o > 0; o >>= 1) w += __shfl_down_sync(0xffu, w, o);
        if (t == 0) red[0] = w;
    }
    __syncthreads();
    float inv = rsqrtf(red[0]);
    uint4 o;
    o.x = packh(v0.x * inv, v0.y * inv);
    o.y = packh(v0.z * inv, v0.w * inv);
    o.z = packh(v1.x * inv, v1.y * inv);
    o.w = packh(v1.z * inv, v1.w * inv);
    ((uint4*)g_xh)[b * (D_ / 8) + t] = o;
}

// ---------------------------------------------------------------------------
// Kernel 2: fp16 GEMM  C[256,16384] = xh @ tempV^T
// CTA 256x64 (tempV read once). BKH=64: 32 chunks, 2 barriers/chunk.
// A: fp16 smem double buffer (cp.async). B: fp32 cp.async -> single staging
// buffer -> cvt -> fp16 double buffer. Inner loop: pure LDSM + HMMA.
// ---------------------------------------------------------------------------
#define BMT 256
#define BNT 64
#define BKH 64                    // halfs per K chunk
#define NCHG (D_ / BKH)           // 32
#define ROWA 144                  // A/B16 row: 128 B data + 16 pad (LDSM-safe)
#define ROWB32 288                // B fp32 row: 256 B data + 32 pad
#define ASTG (BMT * ROWA)         // 36864 B
#define B16S (BNT * ROWA)         // 9216 B
#define B32S (BNT * ROWB32)       // 18432 B
#define GEMM_SMEM (2 * ASTG + 2 * B16S + B32S)   // 110592 B

__global__ void __launch_bounds__(256, 2) kgemm(const float* __restrict__ Bmat) {
    extern __shared__ char sm[];
    uint32_t sbase = smem_u32(sm);
    int t = threadIdx.x, lane = t & 31, wid = t >> 5;
    int warp_m = (wid & 3) * 64, warp_n = (wid >> 2) * 32;
    int gid = lane >> 2, tig = lane & 3;
    int nBase = blockIdx.x * BNT;

    float acc[4][4][4];
    #pragma unroll
    for (int i = 0; i < 4; i++)
        #pragma unroll
        for (int j = 0; j < 4; j++)
            #pragma unroll
            for (int q = 0; q < 4; q++) acc[i][j][q] = 0.f;

    const char* xhb = (const char*)g_xh;
    uint32_t b32b = sbase + 2 * ASTG + 2 * B16S;

    auto loadA = [&](int stage, int c) {
        int k0 = c * BKH;
        uint32_t As = sbase + stage * ASTG;
        #pragma unroll
        for (int r = 0; r < 8; r++) {
            int i = t + r * 256, row = i >> 3, q = i & 7;
            cpa16(As + (uint32_t)(row * ROWA + q * 16),
                  xhb + ((size_t)row * D_ + k0 + q * 8) * 2);
        }
    };
    auto loadB32 = [&](int c) {
        int k0 = c * BKH;
        #pragma unroll
        for (int r = 0; r < 4; r++) {
            int i = t + r * 256, row = i >> 4, q = i & 15;
            cpa16(b32b + (uint32_t)(row * ROWB32 + q * 16),
                  Bmat + (size_t)(nBase + row) * D_ + k0 + q * 4);
        }
    };
    auto cvtB = [&](int stage) {
        int r = t >> 2, c4 = t & 3;
        uint32_t rd = b32b + (uint32_t)(r * ROWB32 + c4 * 64);
        uint32_t wr = sbase + 2 * ASTG + stage * B16S + (uint32_t)(r * ROWA + c4 * 32);
        float4 u0, u1, u2, u3;
        asm volatile("ld.shared.v4.f32 {%0,%1,%2,%3}, [%4];"
                     : "=f"(u0.x), "=f"(u0.y), "=f"(u0.z), "=f"(u0.w) : "r"(rd));
        asm volatile("ld.shared.v4.f32 {%0,%1,%2,%3}, [%4];"
                     : "=f"(u1.x), "=f"(u1.y), "=f"(u1.z), "=f"(u1.w) : "r"(rd + 16));
        asm volatile("ld.shared.v4.f32 {%0,%1,%2,%3}, [%4];"
                     : "=f"(u2.x), "=f"(u2.y), "=f"(u2.z), "=f"(u2.w) : "r"(rd + 32));
        asm volatile("ld.shared.v4.f32 {%0,%1,%2,%3}, [%4];"
                     : "=f"(u3.x), "=f"(u3.y), "=f"(u3.z), "=f"(u3.w) : "r"(rd + 48));
        uint32_t p0 = packh(u0.x, u0.y), p1 = packh(u0.z, u0.w);
        uint32_t p2 = packh(u1.x, u1.y), p3 = packh(u1.z, u1.w);
        uint32_t p4 = packh(u2.x, u2.y), p5 = packh(u2.z, u2.w);
        uint32_t p6 = packh(u3.x, u3.y), p7 = packh(u3.z, u3.w);
        asm volatile("st.shared.v4.b32 [%0], {%1,%2,%3,%4};"
                     :: "r"(wr), "r"(p0), "r"(p1), "r"(p2), "r"(p3) : "memory");
        asm volatile("st.shared.v4.b32 [%0], {%1,%2,%3,%4};"
                     :: "r"(wr + 16), "r"(p4), "r"(p5), "r"(p6), "r"(p7) : "memory");
    };

    uint32_t aoff = (uint32_t)((lane & 15) * ROWA + (lane >> 4) * 16);
    uint32_t boff = (uint32_t)(((lane & 7) + ((lane >> 4) << 3)) * ROWA
                               + (((lane >> 3) & 1) * 16));

    loadA(0, 0);
    loadB32(0);
    asm volatile("cp.async.commit_group;" ::: "memory");

    for (int c = 0; c < NCHG; c++) {
        int s = c & 1;
        asm volatile("cp.async.wait_group 0;" ::: "memory");
        __syncthreads();
        cvtB(s);                       // B32 -> fp16 stage s
        __syncthreads();
        if (c + 1 < NCHG) {            // B32 buffer free now; prefetch c+1
            loadA(s ^ 1, c + 1);
            loadB32(c + 1);
        }
        asm volatile("cp.async.commit_group;" ::: "memory");

        uint32_t As = sbase + s * ASTG;
        uint32_t Bs = sbase + 2 * ASTG + s * B16S;
        #pragma unroll
        for (int kk = 0; kk < 4; kk++) {
            uint32_t a[4][4], b[4][2];
            #pragma unroll
            for (int mt = 0; mt < 4; mt++) {
                uint32_t ad = As + (uint32_t)((warp_m + mt * 16) * ROWA + kk * 32) + aoff;
                LDSM4(a[mt][0], a[mt][1], a[mt][2], a[mt][3], ad);
            }
            #pragma unroll
            for (int np = 0; np < 2; np++) {
                uint32_t bd = Bs + (uint32_t)((warp_n + np * 16) * ROWA + kk * 32) + boff;
                LDSM4(b[2 * np][0], b[2 * np][1], b[2 * np + 1][0], b[2 * np + 1][1], bd);
            }
            #pragma unroll
            for (int mt = 0; mt < 4; mt++)
                #pragma unroll
                for (int nt = 0; nt < 4; nt++)
                    asm volatile(
                        "mma.sync.aligned.m16n8k16.row.col.f32.f16.f16.f32 "
                        "{%0,%1,%2,%3},{%4,%5,%6,%7},{%8,%9},{%0,%1,%2,%3};"
                        : "+f"(acc[mt][nt][0]), "+f"(acc[mt][nt][1]),
                          "+f"(acc[mt][nt][2]), "+f"(acc[mt][nt][3])
                        : "r"(a[mt][0]), "r"(a[mt][1]), "r"(a[mt][2]), "r"(a[mt][3]),
                          "r"(b[nt][0]), "r"(b[nt][1]));
        }
    }

    #pragma unroll
    for (int mt = 0; mt < 4; mt++) {
        int row0 = warp_m + mt * 16 + gid;
        #pragma unroll
        for (int nt = 0; nt < 4; nt++) {
            int col = nBase + warp_n + nt * 8 + 2 * tig;
            *(float2*)(g_logits + (size_t)row0 * NM + col) =
                make_float2(acc[mt][nt][0], acc[mt][nt][1]);
            *(float2*)(g_logits + (size_t)(row0 + 8) * NM + col) =
                make_float2(acc[mt][nt][2], acc[mt][nt][3]);
        }
    }
}

// ---------------------------------------------------------------------------
// Kernel 3: per-sample reductions; 3-pass radix select + fused finalize
// ---------------------------------------------------------------------------
__device__ __forceinline__ float blockSumF(float v, float* scratch) {
    int t = threadIdx.x;
    #pragma unroll
    for (int o = 16; o > 0; o >>= 1) v += __shfl_down_sync(0xffffffffu, v, o);
    if ((t & 31) == 0) scratch[t >> 5] = v;
    __syncthreads();
    if (t < 8) {
        float w = scratch[t];
        #pragma unroll
        for (int o = 4; o > 0; o >>= 1) w += __shfl_down_sync(0xffu, w, o);
        if (t == 0) scratch[0] = w;
    }
    __syncthreads();
    float r = scratch[0];
    __syncthreads();
    return r;
}

__global__ void __launch_bounds__(256) krow(const int* __restrict__ labels,
                                            const int* __restrict__ cams,
                                            float* __restrict__ out) {
    extern __shared__ float sv[];                 // NM floats (64 KB)
    __shared__ int hist[2048];
    __shared__ float fred[8];
    __shared__ int wtot[8], wexcl[8];
    __shared__ float s_ori[CCAM];
    __shared__ uint32_t s_prefix;
    __shared__ int s_rem;
    __shared__ int s_last;
    __shared__ int sc_cam[B_];
    __shared__ float sce[B_], slk[B_];

    int b = blockIdx.x;
    int t = threadIdx.x;
    int lane = t & 31, wid = t >> 5;

    #pragma unroll
    for (int j = 0; j < 8; j++) hist[t + 256 * j] = 0;
    __syncthreads();

    // ---- load row + pass-0 histogram (bits 31:21) fused ----
    const float4* row4 = (const float4*)(g_logits + (size_t)b * NM);
    #pragma unroll
    for (int j = 0; j < 16; j++) {
        float4 w = row4[t + 256 * j];
        ((float4*)sv)[t + 256 * j] = w;
        atomicAdd(&hist[ordu(w.x) >> 21], 1);
        atomicAdd(&hist[ordu(w.y) >> 21], 1);
        atomicAdd(&hist[ordu(w.z) >> 21], 1);
        atomicAdd(&hist[ordu(w.w) >> 21], 1);
    }
    __syncthreads();

    int cam = cams[b];
    int lab = labels[b];

    // ---- intra-camera CE, fixed shift m=1 (|cosine| <= 1), unmasked ----
    int base = cam * P_;
    float s = 0.f;
    #pragma unroll 4
    for (int i = t; i < P_; i += 256) s += expf((sv[base + i] - 1.0f) * TINV);
    float sall = blockSumF(s, fred);
    if (t == 0) g_ce[b] = TINV + logf(sall) - sv[base + lab] * TINV;
    __syncthreads();

    // ---- capture positives, mask them, fix pass-0 histogram ----
    if (t == 0) {
        #pragma unroll
        for (int c = 0; c < CCAM; c++) {
            float v = sv[lab + P_ * c];
            s_ori[c] = v;
            hist[ordu(v) >> 21] -= 1;
            sv[lab + P_ * c] = -10000.0f;
        }
    }
    __syncthreads();

    // ---- hierarchical bin selection ----
    uint32_t prefix = 0u;
    int rem = KTOP;

    auto selectBins = [&](int nbpt, int shift) {
        int h[8], tot = 0;
        for (int j = 0; j < nbpt; j++) { h[j] = hist[t * nbpt + j]; tot += h[j]; }
        int suf = tot;
        #pragma unroll
        for (int o = 1; o < 32; o <<= 1) {
            int q = __shfl_down_sync(0xffffffffu, suf, o);
            if (lane + o < 32) suf += q;
        }
        if (lane == 0) wtot[wid] = suf;
        __syncthreads();
        if (t < 8) {
            int w = wtot[t], ws = w;
            #pragma unroll
            for (int o = 1; o < 8; o <<= 1) {
                int q = __shfl_down_sync(0xffu, ws, o);
                if (t + o < 8) ws += q;
            }
            wexcl[t] = ws - w;
        }
        __syncthreads();
        int above = wexcl[wid] + (suf - tot);
        for (int j = nbpt - 1; j >= 0; j--) {
            int incl = above + h[j];
            if (above < rem && rem <= incl) {
                s_prefix = prefix | ((uint32_t)(t * nbpt + j) << shift);
                s_rem = rem - above;
            }
            above = incl;
        }
        __syncthreads();
        prefix = s_prefix;
        rem = s_rem;
    };

    // pass 0: bits 31:21 (2048 bins) — histogram already built
    selectBins(8, 21);

    // pass 1: bits 20:10 (2048 bins)
    __syncthreads();
    #pragma unroll
    for (int j = 0; j < 8; j++) hist[t + 256 * j] = 0;
    __syncthreads();
    #pragma unroll 8
    for (int j = 0; j < NM / 256; j++) {
        uint32_t u = ordu(sv[t + 256 * j]);
        if ((u & 0xFFE00000u) == prefix)
            atomicAdd(&hist[(u >> 10) & 0x7FF], 1);
    }
    __syncthreads();
    selectBins(8, 10);

    // pass 2: bits 9:0 (1024 bins)
    __syncthreads();
    #pragma unroll
    for (int j = 0; j < 4; j++) hist[t + 256 * j] = 0;
    __syncthreads();
    #pragma unroll 8
    for (int j = 0; j < NM / 256; j++) {
        uint32_t u = ordu(sv[t + 256 * j]);
        if ((u & 0xFFFFFC00u) == prefix)
            atomicAdd(&hist[u & 0x3FF], 1);
    }
    __syncthreads();
    selectBins(4, 0);

    uint32_t thr = prefix;
    float tf = (thr & 0x80000000u) ? __uint_as_float(thr ^ 0x80000000u)
                                   : __uint_as_float(~thr);

    // ---- sum exp over values strictly above threshold (m = 1) ----
    float ssum = 0.f;
    #pragma unroll 8
    for (int j = 0; j < NM / 256; j++) {
        float v = sv[t + 256 * j];
        if (ordu(v) > thr) ssum += expf((v - 1.0f) * TINV);
    }
    float tot = blockSumF(ssum, fred);
    if (t == 0) {
        tot += (float)rem * expf((tf - 1.0f) * TINV);    // ties at threshold
        float mean = 0.f;
        #pragma unroll
        for (int c = 0; c < CCAM; c++) {
            tot += expf((s_ori[c] - 1.0f) * TINV);
            mean += s_ori[c];
        }
        g_lossk[b] = TINV + logf(tot) - mean * TINV / (float)CCAM;
    }

    // ---- fused finalize: last CTA computes segment means ----
    if (t == 0) {
        __threadfence();
        int prev = atomicAdd(&g_cnt, 1);
        s_last = (prev == B_ - 1) ? 1 : 0;
    }
    __syncthreads();
    if (!s_last) return;
    if (t == 0) g_cnt = 0;
    volatile float* vce = g_ce;
    volatile float* vlk = g_lossk;
    sc_cam[t] = cams[t];
    sce[t] = vce[t];
    slk[t] = vlk[t];
    __syncthreads();
    __shared__ float mce[CCAM], mlk[CCAM];
    if (t < CCAM) {
        float sc = 0.f, sl = 0.f; int cnt = 0;
        for (int i = 0; i < B_; i++) {
            if (sc_cam[i] == t) { sc += sce[i]; sl += slk[i]; cnt++; }
        }
        mce[t] = (cnt > 0) ? sc / (float)cnt : 0.f;
        mlk[t] = (cnt > 0) ? sl / (float)cnt : 0.f;
    }
    __syncthreads();
    if (t == 0) {
        float li = 0.f, lk = 0.f;
        #pragma unroll
        for (int c = 0; c < CCAM; c++) { li += mce[c]; lk += mlk[c]; }
        out[0] = li;
        out[1] = 0.5f * lk;                 // LOSS_WEIGHT
    }
}

// ---------------------------------------------------------------------------
extern "C" void kernel_launch(void* const* d_in, const int* in_sizes, int n_in,
                              void* d_out, int out_size) {
    const float* x      = (const float*)d_in[0];
    const int*   labels = (const int*)d_in[1];
    const int*   cams   = (const int*)d_in[2];
    const float* tempV  = (const float*)d_in[3];
    float* out = (float*)d_out;

    knorm<<<B_, 256>>>(x);

    cudaFuncSetAttribute(kgemm, cudaFuncAttributeMaxDynamicSharedMemorySize,
                         GEMM_SMEM);
    kgemm<<<NM / BNT, 256, GEMM_SMEM>>>(tempV);    // 256 CTAs

    cudaFuncSetAttribute(krow, cudaFuncAttributeMaxDynamicSharedMemorySize,
                         NM * (int)sizeof(float) + 1024);
    krow<<<B_, 256, NM * sizeof(float)>>>(labels, cams, out);
}

// round 11
// speedup vs baseline: 1.3899x; 1.2562x over previous
#include <cuda_runtime.h>
#include <cuda_fp16.h>
#include <math.h>
#include <stdint.h>

#define B_    256
#define D_    2048
#define NM    16384      // C_CAM * P
#define P_    2048
#define CCAM  8
#define KTOP  50
#define TINV  (1.0f/0.07f)

// scratch (static device globals — no allocation allowed)
__device__ __align__(16) uint32_t g_xh[B_ * D_ / 2];   // fp16 normalized inputs, 1 MB
__device__ float g_logits[B_ * NM];                    // all_logits, 16 MB
__device__ float g_ce[B_];
__device__ float g_lossk[B_];
__device__ int   g_cnt = 0;                            // last-CTA counter

// ---------------------------------------------------------------------------
__device__ __forceinline__ uint32_t smem_u32(const void* p) {
    uint32_t a;
    asm("{ .reg .u64 t; cvta.to.shared.u64 t, %1; cvt.u32.u64 %0, t; }"
        : "=r"(a) : "l"(p));
    return a;
}
__device__ __forceinline__ void cpa16(uint32_t s, const void* g) {
    asm volatile("cp.async.cg.shared.global [%0], [%1], 16;" :: "r"(s), "l"(g) : "memory");
}
__device__ __forceinline__ uint32_t packh(float lo, float hi) {
    uint32_t r;
    asm("cvt.rn.f16x2.f32 %0, %1, %2;" : "=r"(r) : "f"(hi), "f"(lo));
    return r;
}
__device__ __forceinline__ uint32_t ordu(float f) {
    uint32_t u = __float_as_uint(f);
    return (u & 0x80000000u) ? ~u : (u | 0x80000000u);
}
__device__ __forceinline__ uint32_t sw128(uint32_t off) {
    return off ^ ((off >> 3) & 0x70u);
}
#define LDSM4(r0, r1, r2, r3, a) \
    asm volatile("ldmatrix.sync.aligned.m8n8.x4.shared.b16 {%0,%1,%2,%3}, [%4];" \
                 : "=r"(r0), "=r"(r1), "=r"(r2), "=r"(r3) : "r"(a))
#define COMMIT() asm volatile("cp.async.commit_group;" ::: "memory")
#define WAITG(n) asm volatile("cp.async.wait_group %0;" :: "n"(n) : "memory")

// ---------------------------------------------------------------------------
// Kernel 1: L2-normalize each input row -> fp16 (single pass, register row)
// ---------------------------------------------------------------------------
__global__ void __launch_bounds__(256) knorm(const float* __restrict__ x) {
    __shared__ float red[8];
    int b = blockIdx.x, t = threadIdx.x;
    const float4* row = (const float4*)(x + (size_t)b * D_);
    float4 v0 = row[2 * t], v1 = row[2 * t + 1];
    float s = v0.x * v0.x + v0.y * v0.y + v0.z * v0.z + v0.w * v0.w
            + v1.x * v1.x + v1.y * v1.y + v1.z * v1.z + v1.w * v1.w;
    #pragma unroll
    for (int o = 16; o > 0; o >>= 1) s += __shfl_down_sync(0xffffffffu, s, o);
    if ((t & 31) == 0) red[t >> 5] = s;
    __syncthreads();
    if (t < 8) {
        float w = red[t];
        #pragma unroll
        for (int o = 4; o > 0; o >>= 1) w += __shfl_down_sync(0xffu, w, o);
        if (t == 0) red[0] = w;
    }
    __syncthreads();
    float inv = rsqrtf(red[0]);
    uint4 o;
    o.x = packh(v0.x * inv, v0.y * inv);
    o.y = packh(v0.z * inv, v0.w * inv);
    o.z = packh(v1.x * inv, v1.y * inv);
    o.w = packh(v1.z * inv, v1.w * inv);
    ((uint4*)g_xh)[b * (D_ / 8) + t] = o;
}

// ---------------------------------------------------------------------------
// Kernel 2: fp16 GEMM  C[256,16384] = xh @ tempV^T
// CTA 256x64 (tempV read once). BKH=64. XOR-swizzled A/B16, linear B32 x2.
// Split commit groups: A at distance 1, B32 at distance 2 (DRAM hidden).
// ---------------------------------------------------------------------------
#define BMT 256
#define BNT 64
#define BKH 64                    // halfs per K chunk
#define NCHG (D_ / BKH)           // 32
#define ASTG 32768                // 256 rows * 128 B, SW128 swizzled
#define B16S 8192                 // 64 rows * 128 B, SW128 swizzled
#define B32S 16384                // 64 rows * 256 B, linear
#define GEMM_SMEM (2 * ASTG + 2 * B16S + 2 * B32S)   // 114688 B

__global__ void __launch_bounds__(256, 2) kgemm(const float* __restrict__ Bmat) {
    extern __shared__ char sm[];
    uint32_t sbase = smem_u32(sm);
    int t = threadIdx.x, lane = t & 31, wid = t >> 5;
    int warp_m = (wid & 3) * 64, warp_n = (wid >> 2) * 32;
    int gid = lane >> 2, tig = lane & 3;
    int nBase = blockIdx.x * BNT;

    float acc[4][4][4];
    #pragma unroll
    for (int i = 0; i < 4; i++)
        #pragma unroll
        for (int j = 0; j < 4; j++)
            #pragma unroll
            for (int q = 0; q < 4; q++) acc[i][j][q] = 0.f;

    const char* xhb = (const char*)g_xh;
    uint32_t b16b = sbase + 2 * ASTG;
    uint32_t b32b = sbase + 2 * ASTG + 2 * B16S;

    auto loadA = [&](int stage, int c) {
        int k0 = c * BKH;
        uint32_t As = sbase + stage * ASTG;
        #pragma unroll
        for (int r = 0; r < 8; r++) {
            int i = t + r * 256, row = i >> 3, q = i & 7;
            cpa16(As + sw128((uint32_t)(row * 128 + q * 16)),
                  xhb + ((size_t)row * D_ + k0 + q * 8) * 2);
        }
    };
    auto loadB32 = [&](int stage, int c) {
        int k0 = c * BKH;
        uint32_t B3 = b32b + stage * B32S;
        #pragma unroll
        for (int r = 0; r < 4; r++) {
            int i = t + r * 256, row = i >> 4, q = i & 15;
            cpa16(B3 + (uint32_t)(i * 16),
                  Bmat + (size_t)(nBase + row) * D_ + k0 + q * 4);
        }
    };
    auto cvtB = [&](int stage) {
        uint32_t B3 = b32b + stage * B32S;
        uint32_t B6 = b16b + stage * B16S;
        #pragma unroll
        for (int p = 0; p < 4; p++) {
            float4 u;
            asm volatile("ld.shared.v4.f32 {%0,%1,%2,%3}, [%4];"
                         : "=f"(u.x), "=f"(u.y), "=f"(u.z), "=f"(u.w)
                         : "r"(B3 + (uint32_t)(t * 16 + p * 4096)));
            int e0 = t * 4 + p * 1024;
            int row = e0 >> 6, col = e0 & 63;
            uint32_t p0 = packh(u.x, u.y), p1 = packh(u.z, u.w);
            asm volatile("st.shared.v2.b32 [%0], {%1,%2};"
                         :: "r"(B6 + sw128((uint32_t)(row * 128 + col * 2))),
                            "r"(p0), "r"(p1) : "memory");
        }
    };

    uint32_t swc = (uint32_t)((lane & 7) << 4);
    uint32_t aoff = (uint32_t)((warp_m + (lane & 15)) * 128 + ((lane >> 4) << 4));
    uint32_t boff = (uint32_t)((warp_n + (lane & 7) + ((lane >> 4) << 3)) * 128
                               + (((lane >> 3) & 1) << 4));

    // prologue: order matters (FIFO groups)
    loadB32(0, 0); COMMIT();      // GB: B32(0)
    loadA(0, 0);   COMMIT();      // GA: A(0)
    loadB32(1, 1); COMMIT();      // GB: B32(1)

    for (int c = 0; c < NCHG; c++) {
        int s = c & 1;
        WAITG(2);                  // retires oldest -> B32(c) complete
        __syncthreads();
        cvtB(s);                   // B32[s] -> B16[s]
        __syncthreads();           // B16 visible; B32[s] free
        if (c + 1 < NCHG) loadA(s ^ 1, c + 1);
        COMMIT();                  // GA(c)
        if (c + 2 < NCHG) loadB32(s, c + 2);
        COMMIT();                  // GB(c)
        WAITG(3);                  // retires GA(c-1) -> A(c) complete
        __syncthreads();

        uint32_t As = sbase + s * ASTG;
        uint32_t Bs = b16b + s * B16S;
        #pragma unroll
        for (int kk = 0; kk < 4; kk++) {
            uint32_t a[4][4], b[4][2];
            #pragma unroll
            for (int mt = 0; mt < 4; mt++) {
                uint32_t ad = (As + aoff + (uint32_t)(mt * 2048 + kk * 32)) ^ swc;
                LDSM4(a[mt][0], a[mt][1], a[mt][2], a[mt][3], ad);
            }
            #pragma unroll
            for (int np = 0; np < 2; np++) {
                uint32_t bd = (Bs + boff + (uint32_t)(np * 2048 + kk * 32)) ^ swc;
                LDSM4(b[2 * np][0], b[2 * np][1], b[2 * np + 1][0], b[2 * np + 1][1], bd);
            }
            #pragma unroll
            for (int mt = 0; mt < 4; mt++)
                #pragma unroll
                for (int nt = 0; nt < 4; nt++)
                    asm volatile(
                        "mma.sync.aligned.m16n8k16.row.col.f32.f16.f16.f32 "
                        "{%0,%1,%2,%3},{%4,%5,%6,%7},{%8,%9},{%0,%1,%2,%3};"
                        : "+f"(acc[mt][nt][0]), "+f"(acc[mt][nt][1]),
                          "+f"(acc[mt][nt][2]), "+f"(acc[mt][nt][3])
                        : "r"(a[mt][0]), "r"(a[mt][1]), "r"(a[mt][2]), "r"(a[mt][3]),
                          "r"(b[nt][0]), "r"(b[nt][1]));
        }
    }

    #pragma unroll
    for (int mt = 0; mt < 4; mt++) {
        int row0 = warp_m + mt * 16 + gid;
        #pragma unroll
        for (int nt = 0; nt < 4; nt++) {
            int col = nBase + warp_n + nt * 8 + 2 * tig;
            *(float2*)(g_logits + (size_t)row0 * NM + col) =
                make_float2(acc[mt][nt][0], acc[mt][nt][1]);
            *(float2*)(g_logits + (size_t)(row0 + 8) * NM + col) =
                make_float2(acc[mt][nt][2], acc[mt][nt][3]);
        }
    }
}

// ---------------------------------------------------------------------------
// Kernel 3: per-sample reductions; 3-pass radix select + fused finalize
// 512 threads per CTA (halved per-thread scan trip counts)
// ---------------------------------------------------------------------------
#define KRT 512

__device__ __forceinline__ float blockSumF512(float v, float* scratch) {
    int t = threadIdx.x;
    #pragma unroll
    for (int o = 16; o > 0; o >>= 1) v += __shfl_down_sync(0xffffffffu, v, o);
    if ((t & 31) == 0) scratch[t >> 5] = v;
    __syncthreads();
    if (t < 16) {
        float w = scratch[t];
        #pragma unroll
        for (int o = 8; o > 0; o >>= 1) w += __shfl_down_sync(0xffffu, w, o);
        if (t == 0) scratch[0] = w;
    }
    __syncthreads();
    float r = scratch[0];
    __syncthreads();
    return r;
}

__global__ void __launch_bounds__(KRT) krow(const int* __restrict__ labels,
                                            const int* __restrict__ cams,
                                            float* __restrict__ out) {
    extern __shared__ float sv[];                 // NM floats (64 KB)
    __shared__ int hist[2048];
    __shared__ float fred[16];
    __shared__ int wtot[16], wexcl[16];
    __shared__ float s_ori[CCAM];
    __shared__ uint32_t s_prefix;
    __shared__ int s_rem;
    __shared__ int s_last;
    __shared__ int sc_cam[B_];
    __shared__ float sce[B_], slk[B_];

    int b = blockIdx.x;
    int t = threadIdx.x;
    int lane = t & 31, wid = t >> 5;

    #pragma unroll
    for (int j = 0; j < 4; j++) hist[t + KRT * j] = 0;
    __syncthreads();

    // ---- load row + pass-0 histogram (bits 31:21) fused ----
    const float4* row4 = (const float4*)(g_logits + (size_t)b * NM);
    #pragma unroll
    for (int j = 0; j < 8; j++) {
        float4 w = row4[t + KRT * j];
        ((float4*)sv)[t + KRT * j] = w;
        atomicAdd(&hist[ordu(w.x) >> 21], 1);
        atomicAdd(&hist[ordu(w.y) >> 21], 1);
        atomicAdd(&hist[ordu(w.z) >> 21], 1);
        atomicAdd(&hist[ordu(w.w) >> 21], 1);
    }
    __syncthreads();

    int cam = cams[b];
    int lab = labels[b];

    // ---- intra-camera CE, fixed shift m=1 (|cosine| <= 1), unmasked ----
    int base = cam * P_;
    float s = 0.f;
    #pragma unroll
    for (int j = 0; j < P_ / KRT; j++) s += expf((sv[base + t + KRT * j] - 1.0f) * TINV);
    float sall = blockSumF512(s, fred);
    if (t == 0) g_ce[b] = TINV + logf(sall) - sv[base + lab] * TINV;
    __syncthreads();

    // ---- capture positives, mask them, fix pass-0 histogram ----
    if (t == 0) {
        #pragma unroll
        for (int c = 0; c < CCAM; c++) {
            float v = sv[lab + P_ * c];
            s_ori[c] = v;
            hist[ordu(v) >> 21] -= 1;
            sv[lab + P_ * c] = -10000.0f;
        }
    }
    __syncthreads();

    // ---- hierarchical bin selection (512 threads, 16 warps) ----
    uint32_t prefix = 0u;
    int rem = KTOP;

    auto selectBins = [&](int nbpt, int shift) {
        int h[4], tot = 0;
        for (int j = 0; j < nbpt; j++) { h[j] = hist[t * nbpt + j]; tot += h[j]; }
        int suf = tot;
        #pragma unroll
        for (int o = 1; o < 32; o <<= 1) {
            int q = __shfl_down_sync(0xffffffffu, suf, o);
            if (lane + o < 32) suf += q;
        }
        if (lane == 0) wtot[wid] = suf;
        __syncthreads();
        if (t < 16) {
            int w = wtot[t], ws = w;
            #pragma unroll
            for (int o = 1; o < 16; o <<= 1) {
                int q = __shfl_down_sync(0xffffu, ws, o);
                if (t + o < 16) ws += q;
            }
            wexcl[t] = ws - w;
        }
        __syncthreads();
        int above = wexcl[wid] + (suf - tot);
        for (int j = nbpt - 1; j >= 0; j--) {
            int incl = above + h[j];
            if (above < rem && rem <= incl) {
                s_prefix = prefix | ((uint32_t)(t * nbpt + j) << shift);
                s_rem = rem - above;
            }
            above = incl;
        }
        __syncthreads();
        prefix = s_prefix;
        rem = s_rem;
    };

    // pass 0: bits 31:21 (2048 bins) — histogram already built
    selectBins(4, 21);

    // pass 1: bits 20:10 (2048 bins)
    __syncthreads();
    #pragma unroll
    for (int j = 0; j < 4; j++) hist[t + KRT * j] = 0;
    __syncthreads();
    #pragma unroll
    for (int j = 0; j < NM / KRT; j++) {
        uint32_t u = ordu(sv[t + KRT * j]);
        if ((u & 0xFFE00000u) == prefix)
            atomicAdd(&hist[(u >> 10) & 0x7FF], 1);
    }
    __syncthreads();
    selectBins(4, 10);

    // pass 2: bits 9:0 (1024 bins)
    __syncthreads();
    #pragma unroll
    for (int j = 0; j < 2; j++) hist[t + KRT * j] = 0;
    __syncthreads();
    #pragma unroll
    for (int j = 0; j < NM / KRT; j++) {
        uint32_t u = ordu(sv[t + KRT * j]);
        if ((u & 0xFFFFFC00u) == prefix)
            atomicAdd(&hist[u & 0x3FF], 1);
    }
    __syncthreads();
    selectBins(2, 0);

    uint32_t thr = prefix;
    float tf = (thr & 0x80000000u) ? __uint_as_float(thr ^ 0x80000000u)
                                   : __uint_as_float(~thr);

    // ---- sum exp over values strictly above threshold (m = 1) ----
    float ssum = 0.f;
    #pragma unroll
    for (int j = 0; j < NM / KRT; j++) {
        float v = sv[t + KRT * j];
        if (ordu(v) > thr) ssum += expf((v - 1.0f) * TINV);
    }
    float tot = blockSumF512(ssum, fred);
    if (t == 0) {
        tot += (float)rem * expf((tf - 1.0f) * TINV);    // ties at threshold
        float mean = 0.f;
        #pragma unroll
        for (int c = 0; c < CCAM; c++) {
            tot += expf((s_ori[c] - 1.0f) * TINV);
            mean += s_ori[c];
        }
        g_lossk[b] = TINV + logf(tot) - mean * TINV / (float)CCAM;
    }

    // ---- fused finalize: last CTA computes segment means ----
    if (t == 0) {
        __threadfence();
        int prev = atomicAdd(&g_cnt, 1);
        s_last = (prev == B_ - 1) ? 1 : 0;
    }
    __syncthreads();
    if (!s_last) return;
    if (t == 0) g_cnt = 0;
    volatile float* vce = g_ce;
    volatile float* vlk = g_lossk;
    if (t < B_) {
        sc_cam[t] = cams[t];
        sce[t] = vce[t];
        slk[t] = vlk[t];
    }
    __syncthreads();
    __shared__ float mce[CCAM], mlk[CCAM];
    if (t < CCAM) {
        float sc = 0.f, sl = 0.f; int cnt = 0;
        for (int i = 0; i < B_; i++) {
            if (sc_cam[i] == t) { sc += sce[i]; sl += slk[i]; cnt++; }
        }
        mce[t] = (cnt > 0) ? sc / (float)cnt : 0.f;
        mlk[t] = (cnt > 0) ? sl / (float)cnt : 0.f;
    }
    __syncthreads();
    if (t == 0) {
        float li = 0.f, lk = 0.f;
        #pragma unroll
        for (int c = 0; c < CCAM; c++) { li += mce[c]; lk += mlk[c]; }
        out[0] = li;
        out[1] = 0.5f * lk;                 // LOSS_WEIGHT
    }
}

// ---------------------------------------------------------------------------
extern "C" void kernel_launch(void* const* d_in, const int* in_sizes, int n_in,
                              void* d_out, int out_size) {
    const float* x      = (const float*)d_in[0];
    const int*   labels = (const int*)d_in[1];
    const int*   cams   = (const int*)d_in[2];
    const float* tempV  = (const float*)d_in[3];
    float* out = (float*)d_out;

    knorm<<<B_, 256>>>(x);

    cudaFuncSetAttribute(kgemm, cudaFuncAttributeMaxDynamicSharedMemorySize,
                         GEMM_SMEM);
    kgemm<<<NM / BNT, 256, GEMM_SMEM>>>(tempV);    // 256 CTAs

    cudaFuncSetAttribute(krow, cudaFuncAttributeMaxDynamicSharedMemorySize,
                         NM * (int)sizeof(float) + 1024);
    krow<<<B_, KRT, NM * sizeof(float)>>>(labels, cams, out);
}